// round 11
// baseline (speedup 1.0000x reference)
#include <cuda_runtime.h>
#include <cuda_fp16.h>
#include <cstdint>
#include <math.h>

// ---------------- problem constants ----------------
#define NN      20000
#define EDG     320000
#define ETOT    (EDG + NN)
#define FIN     512
#define HC12    256
#define HC3     64
#define NGRAPH  64
#define NCLASS  5
#define SLOPE   0.2f
#define EPS_BN  1e-5f
#define NBLK1   ((NN + 255) / 256)

#define W1SZ    (FIN * HC12)
#define W2SZ    (HC12 * HC12)
#define W3SZ    (HC12 * HC3)
#define WTOT    (W1SZ + W2SZ + W3SZ)
#define XHSZ    (NN * FIN)

// ---------------- device scratch ----------------
__device__ __half g_xh[(size_t)XHSZ];
__device__ __half g_hlin[(size_t)NN * HC12];
__device__ __half g_hagg[(size_t)NN * HC12];
__device__ float  g_als[NN * 4];
__device__ float  g_ald[NN * 4];
__device__ __half g_wt[WTOT];
__device__ int    g_counts[NN];
__device__ int    g_rowptr[NN + 1];
__device__ int    g_csr_src[ETOT];
__device__ int    g_bsums[128];
__device__ float  g_pooled[NGRAPH * HC3];
__device__ int    g_cnt[NGRAPH];

static inline int cdiv(int a, int b) { return (a + b - 1) / b; }

// ---------------- prep ----------------
__global__ void prep_kernel(const float* __restrict__ x,
                            const float* __restrict__ W1, const float* __restrict__ W2,
                            const float* __restrict__ W3, __half* __restrict__ wt,
                            __half* __restrict__ xh,
                            int* __restrict__ counts, float* __restrict__ pooled,
                            int* __restrict__ cnt) {
    int i = blockIdx.x * blockDim.x + threadIdx.x;
    if (i < XHSZ) xh[i] = __float2half(x[i]);
    if (i < W1SZ) {
        int k = i / HC12, n = i % HC12;
        wt[n * FIN + k] = __float2half(W1[i]);
    } else if (i < W1SZ + W2SZ) {
        int j = i - W1SZ;
        int k = j / HC12, n = j % HC12;
        wt[W1SZ + n * HC12 + k] = __float2half(W2[j]);
    } else if (i < WTOT) {
        int j = i - W1SZ - W2SZ;
        int k = j / HC3, n = j % HC3;
        wt[W1SZ + W2SZ + n * HC12 + k] = __float2half(W3[j]);
    }
    if (i < NN) counts[i] = 0;
    if (i < NGRAPH * HC3) pooled[i] = 0.0f;
    if (i < NGRAPH) cnt[i] = 0;
}

// ---------------- CSR build ----------------
__global__ void hist_kernel(const int* __restrict__ ei, int* __restrict__ counts) {
    int e = blockIdx.x * blockDim.x + threadIdx.x;
    if (e >= ETOT) return;
    int d = (e < EDG) ? ei[EDG + e] : (e - EDG);
    atomicAdd(&counts[d], 1);
}

__global__ void scan_pass1(const int* __restrict__ counts, int* __restrict__ rowptr,
                           int* __restrict__ bsums) {
    __shared__ int wsum[8];
    int b = blockIdx.x, t = threadIdx.x;
    int i = b * 256 + t;
    int x = (i < NN) ? counts[i] : 0;
#pragma unroll
    for (int o = 1; o < 32; o <<= 1) {
        int y = __shfl_up_sync(0xffffffffu, x, o);
        if ((t & 31) >= o) x += y;
    }
    if ((t & 31) == 31) wsum[t >> 5] = x;
    __syncthreads();
    if (t < 8) {
        int y = wsum[t];
#pragma unroll
        for (int o = 1; o < 8; o <<= 1) {
            int z = __shfl_up_sync(0xffu, y, o);
            if (t >= o) y += z;
        }
        wsum[t] = y;
    }
    __syncthreads();
    int off = (t >= 32) ? wsum[(t >> 5) - 1] : 0;
    int incl = x + off;
    if (i < NN) rowptr[i + 1] = incl;
    if (t == 255) bsums[b] = incl;
}

__global__ void scan_fixup(int* __restrict__ rowptr, const int* __restrict__ bsums) {
    int b = blockIdx.x, t = threadIdx.x;
    if (b == 0) { if (t == 0) rowptr[0] = 0; return; }
    __shared__ int red[8];
    int v = 0;
    for (int j = t; j < b; j += 256) v += bsums[j];
#pragma unroll
    for (int o = 16; o; o >>= 1) v += __shfl_down_sync(0xffffffffu, v, o);
    if ((t & 31) == 0) red[t >> 5] = v;
    __syncthreads();
    if (t < 8) {
        int y = red[t];
#pragma unroll
        for (int o = 4; o; o >>= 1) y += __shfl_down_sync(0xffu, y, o);
        if (t == 0) red[0] = y;
    }
    __syncthreads();
    int off = red[0];
    int i = b * 256 + t;
    if (i < NN) rowptr[i + 1] += off;
}

__global__ void scatter_kernel(const int* __restrict__ ei,
                               const int* __restrict__ rowptr,
                               int* __restrict__ counts,
                               int* __restrict__ csr_src) {
    int e = blockIdx.x * blockDim.x + threadIdx.x;
    if (e >= ETOT) return;
    int s, d;
    if (e < EDG) { s = ei[e]; d = ei[EDG + e]; }
    else         { s = d = e - EDG; }
    int pos = rowptr[d] + atomicSub(&counts[d], 1) - 1;
    csr_src[pos] = s;
}

// ---------------- cp.async helpers ----------------
__device__ __forceinline__ void cpa16(unsigned int dst, const void* src) {
    asm volatile("cp.async.cg.shared.global [%0], [%1], 16;\n" :: "r"(dst), "l"(src));
}
__device__ __forceinline__ void cp_commit() { asm volatile("cp.async.commit_group;\n"); }
template <int Ngrp>
__device__ __forceinline__ void cp_wait() { asm volatile("cp.async.wait_group %0;\n" :: "n"(Ngrp)); }

__device__ __forceinline__ void mma_f16(float* d, const unsigned* a, const unsigned* b) {
    asm volatile(
        "mma.sync.aligned.m16n8k16.row.col.f32.f16.f16.f32 "
        "{%0,%1,%2,%3}, {%4,%5,%6,%7}, {%8,%9}, {%0,%1,%2,%3};\n"
        : "+f"(d[0]), "+f"(d[1]), "+f"(d[2]), "+f"(d[3])
        : "r"(a[0]), "r"(a[1]), "r"(a[2]), "r"(a[3]), "r"(b[0]), "r"(b[1]));
}

// inline accumulate helper (replaces buggy macro)
__device__ __forceinline__ void acc8(float* acc, uint4 u, float wgt) {
    float2 f;
    f = __half22float2(*reinterpret_cast<__half2*>(&u.x)); acc[0] += wgt * f.x; acc[1] += wgt * f.y;
    f = __half22float2(*reinterpret_cast<__half2*>(&u.y)); acc[2] += wgt * f.x; acc[3] += wgt * f.y;
    f = __half22float2(*reinterpret_cast<__half2*>(&u.z)); acc[4] += wgt * f.x; acc[5] += wgt * f.y;
    f = __half22float2(*reinterpret_cast<__half2*>(&u.w)); acc[6] += wgt * f.x; acc[7] += wgt * f.y;
}

// ---------------- fp16 GEMM + fused attention-logit epilogue ----------------
template <int BN, int WRM, int WRN, int Hv>
__global__ __launch_bounds__(256, 3) void gemm_attn(const __half* __restrict__ A,
                                                    const __half* __restrict__ B,
                                                    __half* __restrict__ C,
                                                    const float* __restrict__ a_s,
                                                    const float* __restrict__ a_d,
                                                    float* __restrict__ al_s,
                                                    float* __restrict__ al_d,
                                                    int M, int N, int K) {
    constexpr int BM = 128, BK = 32;
    constexpr int WM = BM / WRM, WN = BN / WRN;
    constexpr int MT = WM / 16, NT = WN / 8;
    constexpr int AS = BK + 8;
    constexpr int ACH = BM * 4;
    constexpr int BCH = BN * 4;
    constexpr int BLDB = (BCH + 255) / 256;
    constexpr int HB = BN / 64;

    __shared__ __half As[2][BM * AS];
    __shared__ __half Bs[2][BN * AS];
    __shared__ float sS[BM * HB];
    __shared__ float sD[BM * HB];

    int tid = threadIdx.x, lane = tid & 31, wid = tid >> 5;
    int by = blockIdx.y * BM, bx = blockIdx.x * BN;
    int wm = (wid / WRN) * WM, wn = (wid % WRN) * WN;

    float acc[MT][NT][4];
#pragma unroll
    for (int i = 0; i < MT; i++)
#pragma unroll
        for (int j = 0; j < NT; j++)
#pragma unroll
            for (int r = 0; r < 4; r++) acc[i][j][r] = 0.0f;

    const int ntiles = K / BK;

    auto fetch = [&](int kt, int buf) {
        int k0 = kt * BK;
#pragma unroll
        for (int j = 0; j < ACH / 256; j++) {
            int i = tid + j * 256;
            int row = i >> 2, c = i & 3;
            int gr = by + row; if (gr >= M) gr = M - 1;
            unsigned int dst = (unsigned int)__cvta_generic_to_shared(&As[buf][row * AS + c * 8]);
            cpa16(dst, A + (size_t)gr * K + k0 + c * 8);
        }
#pragma unroll
        for (int j = 0; j < BLDB; j++) {
            int i = tid + j * 256;
            if (i < BCH) {
                int row = i >> 2, c = i & 3;
                unsigned int dst = (unsigned int)__cvta_generic_to_shared(&Bs[buf][row * AS + c * 8]);
                cpa16(dst, B + (size_t)(bx + row) * K + k0 + c * 8);
            }
        }
    };
    auto compute = [&](int buf) {
#pragma unroll
        for (int ks = 0; ks < BK; ks += 16) {
            int c0 = ks + 2 * (lane & 3);
            unsigned af[MT][4], bf[NT][2];
#pragma unroll
            for (int mt = 0; mt < MT; mt++) {
                int r0 = wm + mt * 16 + (lane >> 2);
                af[mt][0] = *reinterpret_cast<const unsigned*>(&As[buf][r0 * AS + c0]);
                af[mt][1] = *reinterpret_cast<const unsigned*>(&As[buf][(r0 + 8) * AS + c0]);
                af[mt][2] = *reinterpret_cast<const unsigned*>(&As[buf][r0 * AS + c0 + 8]);
                af[mt][3] = *reinterpret_cast<const unsigned*>(&As[buf][(r0 + 8) * AS + c0 + 8]);
            }
#pragma unroll
            for (int nt = 0; nt < NT; nt++) {
                int n0 = wn + nt * 8 + (lane >> 2);
                bf[nt][0] = *reinterpret_cast<const unsigned*>(&Bs[buf][n0 * AS + c0]);
                bf[nt][1] = *reinterpret_cast<const unsigned*>(&Bs[buf][n0 * AS + c0 + 8]);
            }
#pragma unroll
            for (int mt = 0; mt < MT; mt++)
#pragma unroll
                for (int nt = 0; nt < NT; nt++)
                    mma_f16(acc[mt][nt], af[mt], bf[nt]);
        }
    };

    fetch(0, 0);
    cp_commit();
    for (int kt = 0; kt < ntiles; kt++) {
        int buf = kt & 1;
        if (kt + 1 < ntiles) { fetch(kt + 1, buf ^ 1); cp_commit(); cp_wait<1>(); }
        else                 { cp_wait<0>(); }
        __syncthreads();
        compute(buf);
        __syncthreads();
    }

    // ---- store C (fp16) ----
#pragma unroll
    for (int mt = 0; mt < MT; mt++) {
#pragma unroll
        for (int nt = 0; nt < NT; nt++) {
            int r0 = by + wm + mt * 16 + (lane >> 2);
            int c0 = bx + wn + nt * 8 + 2 * (lane & 3);
            if (r0 < M)
                *reinterpret_cast<__half2*>(&C[(size_t)r0 * N + c0]) =
                    __floats2half2_rn(acc[mt][nt][0], acc[mt][nt][1]);
            if (r0 + 8 < M)
                *reinterpret_cast<__half2*>(&C[(size_t)(r0 + 8) * N + c0]) =
                    __floats2half2_rn(acc[mt][nt][2], acc[mt][nt][3]);
        }
    }

    // ---- fused attention-logit epilogue ----
    for (int i = tid; i < BM * HB; i += 256) { sS[i] = 0.f; sD[i] = 0.f; }
    __syncthreads();

    float as0[NT], as1[NT], ad0[NT], ad1[NT];
#pragma unroll
    for (int nt = 0; nt < NT; nt++) {
        int c = bx + wn + nt * 8 + 2 * (lane & 3);
        as0[nt] = a_s[c]; as1[nt] = a_s[c + 1];
        ad0[nt] = a_d[c]; ad1[nt] = a_d[c + 1];
    }
    int hl = wn >> 6;
#pragma unroll
    for (int mt = 0; mt < MT; mt++) {
        float pslo = 0.f, pshi = 0.f, pdlo = 0.f, pdhi = 0.f;
#pragma unroll
        for (int nt = 0; nt < NT; nt++) {
            pslo += acc[mt][nt][0] * as0[nt] + acc[mt][nt][1] * as1[nt];
            pshi += acc[mt][nt][2] * as0[nt] + acc[mt][nt][3] * as1[nt];
            pdlo += acc[mt][nt][0] * ad0[nt] + acc[mt][nt][1] * ad1[nt];
            pdhi += acc[mt][nt][2] * ad0[nt] + acc[mt][nt][3] * ad1[nt];
        }
        pslo += __shfl_xor_sync(0xffffffffu, pslo, 1);
        pslo += __shfl_xor_sync(0xffffffffu, pslo, 2);
        pshi += __shfl_xor_sync(0xffffffffu, pshi, 1);
        pshi += __shfl_xor_sync(0xffffffffu, pshi, 2);
        pdlo += __shfl_xor_sync(0xffffffffu, pdlo, 1);
        pdlo += __shfl_xor_sync(0xffffffffu, pdlo, 2);
        pdhi += __shfl_xor_sync(0xffffffffu, pdhi, 1);
        pdhi += __shfl_xor_sync(0xffffffffu, pdhi, 2);
        if ((lane & 3) == 0) {
            int r = wm + mt * 16 + (lane >> 2);
            atomicAdd(&sS[r * HB + hl], pslo);
            atomicAdd(&sS[(r + 8) * HB + hl], pshi);
            atomicAdd(&sD[r * HB + hl], pdlo);
            atomicAdd(&sD[(r + 8) * HB + hl], pdhi);
        }
    }
    __syncthreads();
    int headbase = bx >> 6;
    for (int i = tid; i < BM * HB; i += 256) {
        int row = i / HB, h2 = i % HB;
        int gr = by + row;
        if (gr < M) {
            al_s[gr * Hv + headbase + h2] = sS[i];
            al_d[gr * Hv + headbase + h2] = sD[i];
        }
    }
}

// ---------------- aggregation (warp per dst), 4-edge unroll ----------------
template <int HCv, int Hv, int MODE>
__global__ void gat_aggregate_kernel(const __half* __restrict__ hlin,
                                     const int* __restrict__ rowptr,
                                     const int* __restrict__ csr_src,
                                     const float* __restrict__ al_s,
                                     const float* __restrict__ al_d,
                                     const float* __restrict__ bias,
                                     const float* __restrict__ gamma,
                                     const float* __restrict__ beta,
                                     const float* __restrict__ mean,
                                     const float* __restrict__ var,
                                     __half* __restrict__ out,
                                     const int* __restrict__ batch,
                                     float* __restrict__ pooled,
                                     int* __restrict__ cnt) {
    int gw = (blockIdx.x * blockDim.x + threadIdx.x) >> 5;
    int lane = threadIdx.x & 31;
    if (gw >= NN) return;
    const int CPL = HCv / 32;
    int head = (lane * CPL) >> 6;
    float acc[CPL];
#pragma unroll
    for (int j = 0; j < CPL; j++) acc[j] = 0.f;
    float wsum = 0.f;
    float ald_h = __ldg(&al_d[gw * Hv + head]);

    int beg = rowptr[gw], end = rowptr[gw + 1];
    int p = beg;
    for (; p + 4 <= end; p += 4) {
        int s0 = __ldg(&csr_src[p]);
        int s1 = __ldg(&csr_src[p + 1]);
        int s2 = __ldg(&csr_src[p + 2]);
        int s3 = __ldg(&csr_src[p + 3]);
        if (CPL == 8) {
            uint4 u0 = *reinterpret_cast<const uint4*>(hlin + (size_t)s0 * HCv + lane * 8);
            uint4 u1 = *reinterpret_cast<const uint4*>(hlin + (size_t)s1 * HCv + lane * 8);
            uint4 u2 = *reinterpret_cast<const uint4*>(hlin + (size_t)s2 * HCv + lane * 8);
            uint4 u3 = *reinterpret_cast<const uint4*>(hlin + (size_t)s3 * HCv + lane * 8);
            float e0 = __ldg(&al_s[s0 * Hv + head]) + ald_h;
            float e1 = __ldg(&al_s[s1 * Hv + head]) + ald_h;
            float e2 = __ldg(&al_s[s2 * Hv + head]) + ald_h;
            float e3 = __ldg(&al_s[s3 * Hv + head]) + ald_h;
            e0 = (e0 > 0.f) ? e0 : SLOPE * e0;
            e1 = (e1 > 0.f) ? e1 : SLOPE * e1;
            e2 = (e2 > 0.f) ? e2 : SLOPE * e2;
            e3 = (e3 > 0.f) ? e3 : SLOPE * e3;
            float w0 = __expf(e0), w1 = __expf(e1), w2 = __expf(e2), w3 = __expf(e3);
            wsum += (w0 + w1) + (w2 + w3);
            acc8(acc, u0, w0); acc8(acc, u1, w1); acc8(acc, u2, w2); acc8(acc, u3, w3);
        } else {
            __half2 a0 = *reinterpret_cast<const __half2*>(hlin + (size_t)s0 * HCv + lane * 2);
            __half2 a1 = *reinterpret_cast<const __half2*>(hlin + (size_t)s1 * HCv + lane * 2);
            __half2 a2 = *reinterpret_cast<const __half2*>(hlin + (size_t)s2 * HCv + lane * 2);
            __half2 a3 = *reinterpret_cast<const __half2*>(hlin + (size_t)s3 * HCv + lane * 2);
            float e0 = __ldg(&al_s[s0 * Hv + head]) + ald_h;
            float e1 = __ldg(&al_s[s1 * Hv + head]) + ald_h;
            float e2 = __ldg(&al_s[s2 * Hv + head]) + ald_h;
            float e3 = __ldg(&al_s[s3 * Hv + head]) + ald_h;
            e0 = (e0 > 0.f) ? e0 : SLOPE * e0;
            e1 = (e1 > 0.f) ? e1 : SLOPE * e1;
            e2 = (e2 > 0.f) ? e2 : SLOPE * e2;
            e3 = (e3 > 0.f) ? e3 : SLOPE * e3;
            float w0 = __expf(e0), w1 = __expf(e1), w2 = __expf(e2), w3 = __expf(e3);
            wsum += (w0 + w1) + (w2 + w3);
            float2 f;
            f = __half22float2(a0); acc[0] += w0 * f.x; acc[1] += w0 * f.y;
            f = __half22float2(a1); acc[0] += w1 * f.x; acc[1] += w1 * f.y;
            f = __half22float2(a2); acc[0] += w2 * f.x; acc[1] += w2 * f.y;
            f = __half22float2(a3); acc[0] += w3 * f.x; acc[1] += w3 * f.y;
        }
    }
    for (; p < end; p++) {
        int s0 = __ldg(&csr_src[p]);
        float e0 = __ldg(&al_s[s0 * Hv + head]) + ald_h;
        e0 = (e0 > 0.f) ? e0 : SLOPE * e0;
        float w0 = __expf(e0);
        wsum += w0;
        if (CPL == 8) {
            uint4 u0 = *reinterpret_cast<const uint4*>(hlin + (size_t)s0 * HCv + lane * 8);
            acc8(acc, u0, w0);
        } else {
            float2 a = __half22float2(*reinterpret_cast<const __half2*>(hlin + (size_t)s0 * HCv + lane * 2));
            acc[0] += w0 * a.x;
            acc[1] += w0 * a.y;
        }
    }

    float inv = 1.0f / (wsum + 1e-16f);
    if (MODE == 0) {
        float r[CPL];
#pragma unroll
        for (int j = 0; j < CPL; j++) {
            int c = lane * CPL + j;
            float v = acc[j] * inv + bias[c];
            v = (v - mean[c]) * rsqrtf(var[c] + EPS_BN) * gamma[c] + beta[c];
            r[j] = (v > 0.f) ? v : 0.f;
        }
        if (CPL == 8) {
            __half2 p0 = __floats2half2_rn(r[0], r[1]);
            __half2 p1 = __floats2half2_rn(r[2], r[3]);
            __half2 p2 = __floats2half2_rn(r[4], r[5]);
            __half2 p3 = __floats2half2_rn(r[6], r[7]);
            uint4 u;
            u.x = *reinterpret_cast<unsigned*>(&p0);
            u.y = *reinterpret_cast<unsigned*>(&p1);
            u.z = *reinterpret_cast<unsigned*>(&p2);
            u.w = *reinterpret_cast<unsigned*>(&p3);
            *reinterpret_cast<uint4*>(out + (size_t)gw * HCv + lane * 8) = u;
        }
    } else {
        int b = __ldg(&batch[gw]);
        float v0 = acc[0] * inv + bias[lane * 2];
        float v1 = acc[1] * inv + bias[lane * 2 + 1];
        v0 = (v0 > 0.f) ? v0 : 0.f;
        v1 = (v1 > 0.f) ? v1 : 0.f;
        atomicAdd(&pooled[b * HC3 + lane * 2], v0);
        atomicAdd(&pooled[b * HC3 + lane * 2 + 1], v1);
        if (lane == 0) atomicAdd(&cnt[b], 1);
    }
}

// ---------------- final MLP ----------------
__global__ void mlp_kernel(const float* __restrict__ pooled, const int* __restrict__ cnt,
                           const float* __restrict__ w1, const float* __restrict__ b1,
                           const float* __restrict__ w2, const float* __restrict__ b2,
                           float* __restrict__ out) {
    int g = blockIdx.x;
    int t = threadIdx.x;
    __shared__ float m[HC3];
    __shared__ float hid[32];
    float c = (float)cnt[g];
    if (c < 1.0f) c = 1.0f;
    m[t] = pooled[g * HC3 + t] / c;
    __syncthreads();
    if (t < 32) {
        float s = b1[t];
#pragma unroll
        for (int k = 0; k < HC3; k++) s += m[k] * w1[k * 32 + t];
        hid[t] = (s > 0.f) ? s : 0.f;
    }
    __syncthreads();
    if (t < NCLASS) {
        float s = b2[t];
#pragma unroll
        for (int k = 0; k < 32; k++) s += hid[k] * w2[k * NCLASS + t];
        out[g * NCLASS + t] = s;
    }
}

// ---------------- host orchestration ----------------
extern "C" void kernel_launch(void* const* d_in, const int* in_sizes, int n_in,
                              void* d_out, int out_size) {
    const float* x     = (const float*)d_in[0];
    const int*   ei    = (const int*)  d_in[1];
    const int*   batch = (const int*)  d_in[2];
    const float* W1    = (const float*)d_in[3];
    const float* a1s   = (const float*)d_in[4];
    const float* a1d   = (const float*)d_in[5];
    const float* b1    = (const float*)d_in[6];
    const float* bn1g  = (const float*)d_in[7];
    const float* bn1b  = (const float*)d_in[8];
    const float* bn1m  = (const float*)d_in[9];
    const float* bn1v  = (const float*)d_in[10];
    const float* W2    = (const float*)d_in[11];
    const float* a2s   = (const float*)d_in[12];
    const float* a2d   = (const float*)d_in[13];
    const float* b2    = (const float*)d_in[14];
    const float* bn2g  = (const float*)d_in[15];
    const float* bn2b  = (const float*)d_in[16];
    const float* bn2m  = (const float*)d_in[17];
    const float* bn2v  = (const float*)d_in[18];
    const float* W3    = (const float*)d_in[19];
    const float* a3s   = (const float*)d_in[20];
    const float* a3d   = (const float*)d_in[21];
    const float* b3    = (const float*)d_in[22];
    const float* lin1w = (const float*)d_in[23];
    const float* lin1b = (const float*)d_in[24];
    const float* lin2w = (const float*)d_in[25];
    const float* lin2b = (const float*)d_in[26];
    float* out = (float*)d_out;

    __half *xh, *hlin, *hagg, *wt;
    float *als, *ald, *pooled;
    int *counts, *rowptr, *csr_src, *bsums, *cnt;
    cudaGetSymbolAddress((void**)&xh,      g_xh);
    cudaGetSymbolAddress((void**)&hlin,    g_hlin);
    cudaGetSymbolAddress((void**)&hagg,    g_hagg);
    cudaGetSymbolAddress((void**)&wt,      g_wt);
    cudaGetSymbolAddress((void**)&als,     g_als);
    cudaGetSymbolAddress((void**)&ald,     g_ald);
    cudaGetSymbolAddress((void**)&pooled,  g_pooled);
    cudaGetSymbolAddress((void**)&counts,  g_counts);
    cudaGetSymbolAddress((void**)&rowptr,  g_rowptr);
    cudaGetSymbolAddress((void**)&csr_src, g_csr_src);
    cudaGetSymbolAddress((void**)&bsums,   g_bsums);
    cudaGetSymbolAddress((void**)&cnt,     g_cnt);

    const int TB = 256;
    const int edgeBlocks = cdiv(ETOT, TB);
    const int nodeWarpBlocks = cdiv(NN * 32, TB);

    // 0: prep
    prep_kernel<<<cdiv(XHSZ, TB), TB>>>(x, W1, W2, W3, wt, xh, counts, pooled, cnt);
    // 1-2: CSR histogram + scan
    hist_kernel<<<edgeBlocks, TB>>>(ei, counts);
    scan_pass1<<<NBLK1, 256>>>(counts, rowptr, bsums);
    // 3: layer-1 GEMM (profiled launch)
    {
        dim3 grid(HC12 / 128, cdiv(NN, 128));
        gemm_attn<128, 2, 4, 4><<<grid, 256>>>(xh, wt, hlin, a1s, a1d, als, ald, NN, HC12, FIN);
    }
    // 4-5: finish CSR
    scan_fixup<<<NBLK1, 256>>>(rowptr, bsums);
    scatter_kernel<<<edgeBlocks, TB>>>(ei, rowptr, counts, csr_src);
    // 6: layer-1 aggregate
    gat_aggregate_kernel<HC12, 4, 0><<<nodeWarpBlocks, TB>>>(
        hlin, rowptr, csr_src, als, ald, b1, bn1g, bn1b, bn1m, bn1v, hagg, nullptr, nullptr, nullptr);
    // 7-8: layer 2
    {
        dim3 grid(HC12 / 128, cdiv(NN, 128));
        gemm_attn<128, 2, 4, 4><<<grid, 256>>>(hagg, wt + W1SZ, hlin, a2s, a2d, als, ald, NN, HC12, HC12);
        gat_aggregate_kernel<HC12, 4, 0><<<nodeWarpBlocks, TB>>>(
            hlin, rowptr, csr_src, als, ald, b2, bn2g, bn2b, bn2m, bn2v, hagg, nullptr, nullptr, nullptr);
    }
    // 9-10: layer 3 (aggregate fused with mean-pool)
    {
        dim3 grid(HC3 / 64, cdiv(NN, 128));
        gemm_attn<64, 4, 2, 1><<<grid, 256>>>(hagg, wt + W1SZ + W2SZ, hlin, a3s, a3d, als, ald, NN, HC3, HC12);
        gat_aggregate_kernel<HC3, 1, 1><<<nodeWarpBlocks, TB>>>(
            hlin, rowptr, csr_src, als, ald, b3, nullptr, nullptr, nullptr, nullptr,
            nullptr, batch, pooled, cnt);
    }
    // 11: MLP
    mlp_kernel<<<NGRAPH, HC3>>>(pooled, cnt, lin1w, lin1b, lin2w, lin2b, out);

    (void)in_sizes; (void)n_in; (void)out_size;
}

// round 14
// speedup vs baseline: 1.5927x; 1.5927x over previous
#include <cuda_runtime.h>
#include <cuda_fp16.h>
#include <cstdint>
#include <math.h>

// ---------------- problem constants ----------------
#define NN      20000
#define EDG     320000
#define ETOT    (EDG + NN)
#define FIN     512
#define HC12    256
#define HC3     64
#define NGRAPH  64
#define NCLASS  5
#define SLOPE   0.2f
#define EPS_BN  1e-5f
#define NBLK1   ((NN + 255) / 256)

#define W1SZ    (FIN * HC12)
#define W2SZ    (HC12 * HC12)
#define W3SZ    (HC12 * HC3)
#define WTOT    (W1SZ + W2SZ + W3SZ)
#define XHSZ    (NN * FIN)

// ---------------- device scratch ----------------
__device__ __half g_xh[(size_t)XHSZ];
__device__ __half g_hlin[(size_t)NN * HC12];
__device__ __half g_hagg[(size_t)NN * HC12];
__device__ float  g_als[NN * 4];
__device__ float  g_ald[NN * 4];
__device__ __half g_wt[WTOT];
__device__ int    g_counts[NN];
__device__ int    g_rowptr[NN + 1];
__device__ int    g_csr_src[ETOT];
__device__ int    g_bsums[128];
__device__ float  g_pooled[NGRAPH * HC3];
__device__ int    g_cnt[NGRAPH];

static inline int cdiv(int a, int b) { return (a + b - 1) / b; }

// ---------------- prep ----------------
__global__ void prep_kernel(const float* __restrict__ x,
                            const float* __restrict__ W1, const float* __restrict__ W2,
                            const float* __restrict__ W3, __half* __restrict__ wt,
                            __half* __restrict__ xh,
                            int* __restrict__ counts, float* __restrict__ pooled,
                            int* __restrict__ cnt) {
    int i = blockIdx.x * blockDim.x + threadIdx.x;
    if (i < XHSZ) xh[i] = __float2half(x[i]);
    if (i < W1SZ) {
        int k = i / HC12, n = i % HC12;
        wt[n * FIN + k] = __float2half(W1[i]);
    } else if (i < W1SZ + W2SZ) {
        int j = i - W1SZ;
        int k = j / HC12, n = j % HC12;
        wt[W1SZ + n * HC12 + k] = __float2half(W2[j]);
    } else if (i < WTOT) {
        int j = i - W1SZ - W2SZ;
        int k = j / HC3, n = j % HC3;
        wt[W1SZ + W2SZ + n * HC12 + k] = __float2half(W3[j]);
    }
    if (i < NN) counts[i] = 0;
    if (i < NGRAPH * HC3) pooled[i] = 0.0f;
    if (i < NGRAPH) cnt[i] = 0;
}

// ---------------- CSR build ----------------
__global__ void hist_kernel(const int* __restrict__ ei, int* __restrict__ counts) {
    int e = blockIdx.x * blockDim.x + threadIdx.x;
    if (e >= ETOT) return;
    int d = (e < EDG) ? ei[EDG + e] : (e - EDG);
    atomicAdd(&counts[d], 1);
}

__global__ void scan_pass1(const int* __restrict__ counts, int* __restrict__ rowptr,
                           int* __restrict__ bsums) {
    __shared__ int wsum[8];
    int b = blockIdx.x, t = threadIdx.x;
    int i = b * 256 + t;
    int x = (i < NN) ? counts[i] : 0;
#pragma unroll
    for (int o = 1; o < 32; o <<= 1) {
        int y = __shfl_up_sync(0xffffffffu, x, o);
        if ((t & 31) >= o) x += y;
    }
    if ((t & 31) == 31) wsum[t >> 5] = x;
    __syncthreads();
    if (t < 8) {
        int y = wsum[t];
#pragma unroll
        for (int o = 1; o < 8; o <<= 1) {
            int z = __shfl_up_sync(0xffu, y, o);
            if (t >= o) y += z;
        }
        wsum[t] = y;
    }
    __syncthreads();
    int off = (t >= 32) ? wsum[(t >> 5) - 1] : 0;
    int incl = x + off;
    if (i < NN) rowptr[i + 1] = incl;
    if (t == 255) bsums[b] = incl;
}

__global__ void scan_fixup(int* __restrict__ rowptr, const int* __restrict__ bsums) {
    int b = blockIdx.x, t = threadIdx.x;
    if (b == 0) { if (t == 0) rowptr[0] = 0; return; }
    __shared__ int red[8];
    int v = 0;
    for (int j = t; j < b; j += 256) v += bsums[j];
#pragma unroll
    for (int o = 16; o; o >>= 1) v += __shfl_down_sync(0xffffffffu, v, o);
    if ((t & 31) == 0) red[t >> 5] = v;
    __syncthreads();
    if (t < 8) {
        int y = red[t];
#pragma unroll
        for (int o = 4; o; o >>= 1) y += __shfl_down_sync(0xffu, y, o);
        if (t == 0) red[0] = y;
    }
    __syncthreads();
    int off = red[0];
    int i = b * 256 + t;
    if (i < NN) rowptr[i + 1] += off;
}

__global__ void scatter_kernel(const int* __restrict__ ei,
                               const int* __restrict__ rowptr,
                               int* __restrict__ counts,
                               int* __restrict__ csr_src) {
    int e = blockIdx.x * blockDim.x + threadIdx.x;
    if (e >= ETOT) return;
    int s, d;
    if (e < EDG) { s = ei[e]; d = ei[EDG + e]; }
    else         { s = d = e - EDG; }
    int pos = rowptr[d] + atomicSub(&counts[d], 1) - 1;
    csr_src[pos] = s;
}

// ---------------- cp.async helpers ----------------
__device__ __forceinline__ void cpa16(unsigned int dst, const void* src) {
    asm volatile("cp.async.cg.shared.global [%0], [%1], 16;\n" :: "r"(dst), "l"(src));
}
__device__ __forceinline__ void cp_commit() { asm volatile("cp.async.commit_group;\n"); }
template <int Ngrp>
__device__ __forceinline__ void cp_wait() { asm volatile("cp.async.wait_group %0;\n" :: "n"(Ngrp)); }

__device__ __forceinline__ void mma_f16(float* d, const unsigned* a, const unsigned* b) {
    asm volatile(
        "mma.sync.aligned.m16n8k16.row.col.f32.f16.f16.f32 "
        "{%0,%1,%2,%3}, {%4,%5,%6,%7}, {%8,%9}, {%0,%1,%2,%3};\n"
        : "+f"(d[0]), "+f"(d[1]), "+f"(d[2]), "+f"(d[3])
        : "r"(a[0]), "r"(a[1]), "r"(a[2]), "r"(a[3]), "r"(b[0]), "r"(b[1]));
}

// ---------------- fp16 GEMM + fused attention-logit epilogue ----------------
// Small tile (BM=64): acc=32 floats/thread -> ~80 regs natural, smem ~32KB -> 3 CTAs/SM.
template <int BM, int BN, int WRM, int WRN, int Hv>
__global__ __launch_bounds__(256, 3) void gemm_attn(const __half* __restrict__ A,
                                                    const __half* __restrict__ B,
                                                    __half* __restrict__ C,
                                                    const float* __restrict__ a_s,
                                                    const float* __restrict__ a_d,
                                                    float* __restrict__ al_s,
                                                    float* __restrict__ al_d,
                                                    int M, int N, int K) {
    constexpr int BK = 32;
    constexpr int WM = BM / WRM, WN = BN / WRN;
    constexpr int MT = WM / 16, NT = WN / 8;
    constexpr int AS = BK + 8;
    constexpr int ACH = BM * 4;
    constexpr int BCH = BN * 4;
    constexpr int ALDA = (ACH + 255) / 256;
    constexpr int BLDB = (BCH + 255) / 256;
    constexpr int HB = BN / 64;

    __shared__ __half As[2][BM * AS];
    __shared__ __half Bs[2][BN * AS];
    __shared__ float sS[BM * HB];
    __shared__ float sD[BM * HB];

    int tid = threadIdx.x, lane = tid & 31, wid = tid >> 5;
    int by = blockIdx.y * BM, bx = blockIdx.x * BN;
    int wm = (wid / WRN) * WM, wn = (wid % WRN) * WN;

    float acc[MT][NT][4];
#pragma unroll
    for (int i = 0; i < MT; i++)
#pragma unroll
        for (int j = 0; j < NT; j++)
#pragma unroll
            for (int r = 0; r < 4; r++) acc[i][j][r] = 0.0f;

    const int ntiles = K / BK;

    auto fetch = [&](int kt, int buf) {
        int k0 = kt * BK;
#pragma unroll
        for (int j = 0; j < ALDA; j++) {
            int i = tid + j * 256;
            if (i < ACH) {
                int row = i >> 2, c = i & 3;
                int gr = by + row; if (gr >= M) gr = M - 1;
                unsigned int dst = (unsigned int)__cvta_generic_to_shared(&As[buf][row * AS + c * 8]);
                cpa16(dst, A + (size_t)gr * K + k0 + c * 8);
            }
        }
#pragma unroll
        for (int j = 0; j < BLDB; j++) {
            int i = tid + j * 256;
            if (i < BCH) {
                int row = i >> 2, c = i & 3;
                unsigned int dst = (unsigned int)__cvta_generic_to_shared(&Bs[buf][row * AS + c * 8]);
                cpa16(dst, B + (size_t)(bx + row) * K + k0 + c * 8);
            }
        }
    };
    auto compute = [&](int buf) {
#pragma unroll
        for (int ks = 0; ks < BK; ks += 16) {
            int c0 = ks + 2 * (lane & 3);
            unsigned af[MT][4], bf[NT][2];
#pragma unroll
            for (int mt = 0; mt < MT; mt++) {
                int r0 = wm + mt * 16 + (lane >> 2);
                af[mt][0] = *reinterpret_cast<const unsigned*>(&As[buf][r0 * AS + c0]);
                af[mt][1] = *reinterpret_cast<const unsigned*>(&As[buf][(r0 + 8) * AS + c0]);
                af[mt][2] = *reinterpret_cast<const unsigned*>(&As[buf][r0 * AS + c0 + 8]);
                af[mt][3] = *reinterpret_cast<const unsigned*>(&As[buf][(r0 + 8) * AS + c0 + 8]);
            }
#pragma unroll
            for (int nt = 0; nt < NT; nt++) {
                int n0 = wn + nt * 8 + (lane >> 2);
                bf[nt][0] = *reinterpret_cast<const unsigned*>(&Bs[buf][n0 * AS + c0]);
                bf[nt][1] = *reinterpret_cast<const unsigned*>(&Bs[buf][n0 * AS + c0 + 8]);
            }
#pragma unroll
            for (int mt = 0; mt < MT; mt++)
#pragma unroll
                for (int nt = 0; nt < NT; nt++)
                    mma_f16(acc[mt][nt], af[mt], bf[nt]);
        }
    };

    fetch(0, 0);
    cp_commit();
    for (int kt = 0; kt < ntiles; kt++) {
        int buf = kt & 1;
        if (kt + 1 < ntiles) { fetch(kt + 1, buf ^ 1); cp_commit(); cp_wait<1>(); }
        else                 { cp_wait<0>(); }
        __syncthreads();
        compute(buf);
        __syncthreads();
    }

    // ---- store C (fp16) ----
#pragma unroll
    for (int mt = 0; mt < MT; mt++) {
#pragma unroll
        for (int nt = 0; nt < NT; nt++) {
            int r0 = by + wm + mt * 16 + (lane >> 2);
            int c0 = bx + wn + nt * 8 + 2 * (lane & 3);
            if (r0 < M)
                *reinterpret_cast<__half2*>(&C[(size_t)r0 * N + c0]) =
                    __floats2half2_rn(acc[mt][nt][0], acc[mt][nt][1]);
            if (r0 + 8 < M)
                *reinterpret_cast<__half2*>(&C[(size_t)(r0 + 8) * N + c0]) =
                    __floats2half2_rn(acc[mt][nt][2], acc[mt][nt][3]);
        }
    }

    // ---- fused attention-logit epilogue ----
    for (int i = tid; i < BM * HB; i += 256) { sS[i] = 0.f; sD[i] = 0.f; }
    __syncthreads();

    float as0[NT], as1[NT], ad0[NT], ad1[NT];
#pragma unroll
    for (int nt = 0; nt < NT; nt++) {
        int c = bx + wn + nt * 8 + 2 * (lane & 3);
        as0[nt] = a_s[c]; as1[nt] = a_s[c + 1];
        ad0[nt] = a_d[c]; ad1[nt] = a_d[c + 1];
    }
    int hl = wn >> 6;
#pragma unroll
    for (int mt = 0; mt < MT; mt++) {
        float pslo = 0.f, pshi = 0.f, pdlo = 0.f, pdhi = 0.f;
#pragma unroll
        for (int nt = 0; nt < NT; nt++) {
            pslo += acc[mt][nt][0] * as0[nt] + acc[mt][nt][1] * as1[nt];
            pshi += acc[mt][nt][2] * as0[nt] + acc[mt][nt][3] * as1[nt];
            pdlo += acc[mt][nt][0] * ad0[nt] + acc[mt][nt][1] * ad1[nt];
            pdhi += acc[mt][nt][2] * ad0[nt] + acc[mt][nt][3] * ad1[nt];
        }
        pslo += __shfl_xor_sync(0xffffffffu, pslo, 1);
        pslo += __shfl_xor_sync(0xffffffffu, pslo, 2);
        pshi += __shfl_xor_sync(0xffffffffu, pshi, 1);
        pshi += __shfl_xor_sync(0xffffffffu, pshi, 2);
        pdlo += __shfl_xor_sync(0xffffffffu, pdlo, 1);
        pdlo += __shfl_xor_sync(0xffffffffu, pdlo, 2);
        pdhi += __shfl_xor_sync(0xffffffffu, pdhi, 1);
        pdhi += __shfl_xor_sync(0xffffffffu, pdhi, 2);
        if ((lane & 3) == 0) {
            int r = wm + mt * 16 + (lane >> 2);
            atomicAdd(&sS[r * HB + hl], pslo);
            atomicAdd(&sS[(r + 8) * HB + hl], pshi);
            atomicAdd(&sD[r * HB + hl], pdlo);
            atomicAdd(&sD[(r + 8) * HB + hl], pdhi);
        }
    }
    __syncthreads();
    int headbase = bx >> 6;
    for (int i = tid; i < BM * HB; i += 256) {
        int row = i / HB, h2 = i % HB;
        int gr = by + row;
        if (gr < M) {
            al_s[gr * Hv + headbase + h2] = sS[i];
            al_d[gr * Hv + headbase + h2] = sD[i];
        }
    }
}

// ---------------- aggregation (warp per dst), 2-edge unroll (R9 form) ----------------
__device__ __forceinline__ void acc8(float* acc, uint4 u, float wgt) {
    float2 f;
    f = __half22float2(*reinterpret_cast<__half2*>(&u.x)); acc[0] += wgt * f.x; acc[1] += wgt * f.y;
    f = __half22float2(*reinterpret_cast<__half2*>(&u.y)); acc[2] += wgt * f.x; acc[3] += wgt * f.y;
    f = __half22float2(*reinterpret_cast<__half2*>(&u.z)); acc[4] += wgt * f.x; acc[5] += wgt * f.y;
    f = __half22float2(*reinterpret_cast<__half2*>(&u.w)); acc[6] += wgt * f.x; acc[7] += wgt * f.y;
}

template <int HCv, int Hv, int MODE>
__global__ void gat_aggregate_kernel(const __half* __restrict__ hlin,
                                     const int* __restrict__ rowptr,
                                     const int* __restrict__ csr_src,
                                     const float* __restrict__ al_s,
                                     const float* __restrict__ al_d,
                                     const float* __restrict__ bias,
                                     const float* __restrict__ gamma,
                                     const float* __restrict__ beta,
                                     const float* __restrict__ mean,
                                     const float* __restrict__ var,
                                     __half* __restrict__ out,
                                     const int* __restrict__ batch,
                                     float* __restrict__ pooled,
                                     int* __restrict__ cnt) {
    int gw = (blockIdx.x * blockDim.x + threadIdx.x) >> 5;
    int lane = threadIdx.x & 31;
    if (gw >= NN) return;
    const int CPL = HCv / 32;
    int head = (lane * CPL) >> 6;
    float acc[CPL];
#pragma unroll
    for (int j = 0; j < CPL; j++) acc[j] = 0.f;
    float wsum = 0.f;
    float ald_h = __ldg(&al_d[gw * Hv + head]);

    int beg = rowptr[gw], end = rowptr[gw + 1];
    int p = beg;
    for (; p + 2 <= end; p += 2) {
        int s0 = __ldg(&csr_src[p]);
        int s1 = __ldg(&csr_src[p + 1]);
        float e0 = __ldg(&al_s[s0 * Hv + head]) + ald_h;
        float e1 = __ldg(&al_s[s1 * Hv + head]) + ald_h;
        e0 = (e0 > 0.f) ? e0 : SLOPE * e0;
        e1 = (e1 > 0.f) ? e1 : SLOPE * e1;
        float w0 = __expf(e0), w1 = __expf(e1);
        wsum += w0 + w1;
        if (CPL == 8) {
            uint4 u0 = *reinterpret_cast<const uint4*>(hlin + (size_t)s0 * HCv + lane * 8);
            uint4 u1 = *reinterpret_cast<const uint4*>(hlin + (size_t)s1 * HCv + lane * 8);
            acc8(acc, u0, w0);
            acc8(acc, u1, w1);
        } else {
            float2 a = __half22float2(*reinterpret_cast<const __half2*>(hlin + (size_t)s0 * HCv + lane * 2));
            float2 b = __half22float2(*reinterpret_cast<const __half2*>(hlin + (size_t)s1 * HCv + lane * 2));
            acc[0] += w0 * a.x + w1 * b.x;
            acc[1] += w0 * a.y + w1 * b.y;
        }
    }
    if (p < end) {
        int s0 = __ldg(&csr_src[p]);
        float e0 = __ldg(&al_s[s0 * Hv + head]) + ald_h;
        e0 = (e0 > 0.f) ? e0 : SLOPE * e0;
        float w0 = __expf(e0);
        wsum += w0;
        if (CPL == 8) {
            uint4 u0 = *reinterpret_cast<const uint4*>(hlin + (size_t)s0 * HCv + lane * 8);
            acc8(acc, u0, w0);
        } else {
            float2 a = __half22float2(*reinterpret_cast<const __half2*>(hlin + (size_t)s0 * HCv + lane * 2));
            acc[0] += w0 * a.x;
            acc[1] += w0 * a.y;
        }
    }

    float inv = 1.0f / (wsum + 1e-16f);
    if (MODE == 0) {
        float r[CPL];
#pragma unroll
        for (int j = 0; j < CPL; j++) {
            int c = lane * CPL + j;
            float v = acc[j] * inv + bias[c];
            v = (v - mean[c]) * rsqrtf(var[c] + EPS_BN) * gamma[c] + beta[c];
            r[j] = (v > 0.f) ? v : 0.f;
        }
        if (CPL == 8) {
            __half2 p0 = __floats2half2_rn(r[0], r[1]);
            __half2 p1 = __floats2half2_rn(r[2], r[3]);
            __half2 p2 = __floats2half2_rn(r[4], r[5]);
            __half2 p3 = __floats2half2_rn(r[6], r[7]);
            uint4 u;
            u.x = *reinterpret_cast<unsigned*>(&p0);
            u.y = *reinterpret_cast<unsigned*>(&p1);
            u.z = *reinterpret_cast<unsigned*>(&p2);
            u.w = *reinterpret_cast<unsigned*>(&p3);
            *reinterpret_cast<uint4*>(out + (size_t)gw * HCv + lane * 8) = u;
        }
    } else {
        int b = __ldg(&batch[gw]);
        float v0 = acc[0] * inv + bias[lane * 2];
        float v1 = acc[1] * inv + bias[lane * 2 + 1];
        v0 = (v0 > 0.f) ? v0 : 0.f;
        v1 = (v1 > 0.f) ? v1 : 0.f;
        atomicAdd(&pooled[b * HC3 + lane * 2], v0);
        atomicAdd(&pooled[b * HC3 + lane * 2 + 1], v1);
        if (lane == 0) atomicAdd(&cnt[b], 1);
    }
}

// ---------------- final MLP ----------------
__global__ void mlp_kernel(const float* __restrict__ pooled, const int* __restrict__ cnt,
                           const float* __restrict__ w1, const float* __restrict__ b1,
                           const float* __restrict__ w2, const float* __restrict__ b2,
                           float* __restrict__ out) {
    int g = blockIdx.x;
    int t = threadIdx.x;
    __shared__ float m[HC3];
    __shared__ float hid[32];
    float c = (float)cnt[g];
    if (c < 1.0f) c = 1.0f;
    m[t] = pooled[g * HC3 + t] / c;
    __syncthreads();
    if (t < 32) {
        float s = b1[t];
#pragma unroll
        for (int k = 0; k < HC3; k++) s += m[k] * w1[k * 32 + t];
        hid[t] = (s > 0.f) ? s : 0.f;
    }
    __syncthreads();
    if (t < NCLASS) {
        float s = b2[t];
#pragma unroll
        for (int k = 0; k < 32; k++) s += hid[k] * w2[k * NCLASS + t];
        out[g * NCLASS + t] = s;
    }
}

// ---------------- host orchestration ----------------
extern "C" void kernel_launch(void* const* d_in, const int* in_sizes, int n_in,
                              void* d_out, int out_size) {
    const float* x     = (const float*)d_in[0];
    const int*   ei    = (const int*)  d_in[1];
    const int*   batch = (const int*)  d_in[2];
    const float* W1    = (const float*)d_in[3];
    const float* a1s   = (const float*)d_in[4];
    const float* a1d   = (const float*)d_in[5];
    const float* b1    = (const float*)d_in[6];
    const float* bn1g  = (const float*)d_in[7];
    const float* bn1b  = (const float*)d_in[8];
    const float* bn1m  = (const float*)d_in[9];
    const float* bn1v  = (const float*)d_in[10];
    const float* W2    = (const float*)d_in[11];
    const float* a2s   = (const float*)d_in[12];
    const float* a2d   = (const float*)d_in[13];
    const float* b2    = (const float*)d_in[14];
    const float* bn2g  = (const float*)d_in[15];
    const float* bn2b  = (const float*)d_in[16];
    const float* bn2m  = (const float*)d_in[17];
    const float* bn2v  = (const float*)d_in[18];
    const float* W3    = (const float*)d_in[19];
    const float* a3s   = (const float*)d_in[20];
    const float* a3d   = (const float*)d_in[21];
    const float* b3    = (const float*)d_in[22];
    const float* lin1w = (const float*)d_in[23];
    const float* lin1b = (const float*)d_in[24];
    const float* lin2w = (const float*)d_in[25];
    const float* lin2b = (const float*)d_in[26];
    float* out = (float*)d_out;

    __half *xh, *hlin, *hagg, *wt;
    float *als, *ald, *pooled;
    int *counts, *rowptr, *csr_src, *bsums, *cnt;
    cudaGetSymbolAddress((void**)&xh,      g_xh);
    cudaGetSymbolAddress((void**)&hlin,    g_hlin);
    cudaGetSymbolAddress((void**)&hagg,    g_hagg);
    cudaGetSymbolAddress((void**)&wt,      g_wt);
    cudaGetSymbolAddress((void**)&als,     g_als);
    cudaGetSymbolAddress((void**)&ald,     g_ald);
    cudaGetSymbolAddress((void**)&pooled,  g_pooled);
    cudaGetSymbolAddress((void**)&counts,  g_counts);
    cudaGetSymbolAddress((void**)&rowptr,  g_rowptr);
    cudaGetSymbolAddress((void**)&csr_src, g_csr_src);
    cudaGetSymbolAddress((void**)&bsums,   g_bsums);
    cudaGetSymbolAddress((void**)&cnt,     g_cnt);

    const int TB = 256;
    const int edgeBlocks = cdiv(ETOT, TB);
    const int nodeWarpBlocks = cdiv(NN * 32, TB);

    // 0: prep
    prep_kernel<<<cdiv(XHSZ, TB), TB>>>(x, W1, W2, W3, wt, xh, counts, pooled, cnt);
    // 1-2: CSR histogram + scan
    hist_kernel<<<edgeBlocks, TB>>>(ei, counts);
    scan_pass1<<<NBLK1, 256>>>(counts, rowptr, bsums);
    // 3: layer-1 GEMM (profiled launch)
    {
        dim3 grid(HC12 / 128, cdiv(NN, 64));
        gemm_attn<64, 128, 2, 4, 4><<<grid, 256>>>(xh, wt, hlin, a1s, a1d, als, ald, NN, HC12, FIN);
    }
    // 4-5: finish CSR
    scan_fixup<<<NBLK1, 256>>>(rowptr, bsums);
    scatter_kernel<<<edgeBlocks, TB>>>(ei, rowptr, counts, csr_src);
    // 6: layer-1 aggregate
    gat_aggregate_kernel<HC12, 4, 0><<<nodeWarpBlocks, TB>>>(
        hlin, rowptr, csr_src, als, ald, b1, bn1g, bn1b, bn1m, bn1v, hagg, nullptr, nullptr, nullptr);
    // 7-8: layer 2
    {
        dim3 grid(HC12 / 128, cdiv(NN, 64));
        gemm_attn<64, 128, 2, 4, 4><<<grid, 256>>>(hagg, wt + W1SZ, hlin, a2s, a2d, als, ald, NN, HC12, HC12);
        gat_aggregate_kernel<HC12, 4, 0><<<nodeWarpBlocks, TB>>>(
            hlin, rowptr, csr_src, als, ald, b2, bn2g, bn2b, bn2m, bn2v, hagg, nullptr, nullptr, nullptr);
    }
    // 9-10: layer 3 (aggregate fused with mean-pool)
    {
        dim3 grid(HC3 / 64, cdiv(NN, 64));
        gemm_attn<64, 64, 2, 4, 1><<<grid, 256>>>(hagg, wt + W1SZ + W2SZ, hlin, a3s, a3d, als, ald, NN, HC3, HC12);
        gat_aggregate_kernel<HC3, 1, 1><<<nodeWarpBlocks, TB>>>(
            hlin, rowptr, csr_src, als, ald, b3, nullptr, nullptr, nullptr, nullptr,
            nullptr, batch, pooled, cnt);
    }
    // 11: MLP
    mlp_kernel<<<NGRAPH, HC3>>>(pooled, cnt, lin1w, lin1b, lin2w, lin2b, out);

    (void)in_sizes; (void)n_in; (void)out_size;
}

// round 15
// speedup vs baseline: 1.6270x; 1.0216x over previous
#include <cuda_runtime.h>
#include <cuda_fp16.h>
#include <cstdint>
#include <math.h>

// ---------------- problem constants ----------------
#define NN      20000
#define EDG     320000
#define ETOT    (EDG + NN)
#define FIN     512
#define HC12    256
#define HC3     64
#define NGRAPH  64
#define NCLASS  5
#define SLOPE   0.2f
#define EPS_BN  1e-5f
#define NBLK1   ((NN + 255) / 256)

#define W1SZ    (FIN * HC12)
#define W2SZ    (HC12 * HC12)
#define W3SZ    (HC12 * HC3)
#define WTOT    (W1SZ + W2SZ + W3SZ)
#define XHSZ    (NN * FIN)

// ---------------- device scratch ----------------
__device__ __half g_xh[(size_t)XHSZ];
__device__ __half g_hlin[(size_t)NN * HC12];
__device__ __half g_hagg[(size_t)NN * HC12];
__device__ float  g_als[NN * 4];
__device__ float  g_ald[NN * 4];
__device__ __half g_wt[WTOT];
__device__ int    g_counts[NN];
__device__ int    g_rowptr[NN + 1];
__device__ int    g_csr_src[ETOT];
__device__ int    g_bsums[128];
__device__ float  g_pooled[NGRAPH * HC3];
__device__ int    g_cnt[NGRAPH];

static inline int cdiv(int a, int b) { return (a + b - 1) / b; }

// ---------------- prep ----------------
__global__ void prep_kernel(const float* __restrict__ x,
                            const float* __restrict__ W1, const float* __restrict__ W2,
                            const float* __restrict__ W3, __half* __restrict__ wt,
                            __half* __restrict__ xh,
                            int* __restrict__ counts, float* __restrict__ pooled,
                            int* __restrict__ cnt) {
    int i = blockIdx.x * blockDim.x + threadIdx.x;
    if (i < XHSZ) xh[i] = __float2half(x[i]);
    if (i < W1SZ) {
        int k = i / HC12, n = i % HC12;
        wt[n * FIN + k] = __float2half(W1[i]);
    } else if (i < W1SZ + W2SZ) {
        int j = i - W1SZ;
        int k = j / HC12, n = j % HC12;
        wt[W1SZ + n * HC12 + k] = __float2half(W2[j]);
    } else if (i < WTOT) {
        int j = i - W1SZ - W2SZ;
        int k = j / HC3, n = j % HC3;
        wt[W1SZ + W2SZ + n * HC12 + k] = __float2half(W3[j]);
    }
    if (i < NN) counts[i] = 0;
    if (i < NGRAPH * HC3) pooled[i] = 0.0f;
    if (i < NGRAPH) cnt[i] = 0;
}

// ---------------- CSR build ----------------
__global__ void hist_kernel(const int* __restrict__ ei, int* __restrict__ counts) {
    int e = blockIdx.x * blockDim.x + threadIdx.x;
    if (e >= ETOT) return;
    int d = (e < EDG) ? ei[EDG + e] : (e - EDG);
    atomicAdd(&counts[d], 1);
}

__global__ void scan_pass1(const int* __restrict__ counts, int* __restrict__ rowptr,
                           int* __restrict__ bsums) {
    __shared__ int wsum[8];
    int b = blockIdx.x, t = threadIdx.x;
    int i = b * 256 + t;
    int x = (i < NN) ? counts[i] : 0;
#pragma unroll
    for (int o = 1; o < 32; o <<= 1) {
        int y = __shfl_up_sync(0xffffffffu, x, o);
        if ((t & 31) >= o) x += y;
    }
    if ((t & 31) == 31) wsum[t >> 5] = x;
    __syncthreads();
    if (t < 8) {
        int y = wsum[t];
#pragma unroll
        for (int o = 1; o < 8; o <<= 1) {
            int z = __shfl_up_sync(0xffu, y, o);
            if (t >= o) y += z;
        }
        wsum[t] = y;
    }
    __syncthreads();
    int off = (t >= 32) ? wsum[(t >> 5) - 1] : 0;
    int incl = x + off;
    if (i < NN) rowptr[i + 1] = incl;
    if (t == 255) bsums[b] = incl;
}

__global__ void scan_fixup(int* __restrict__ rowptr, const int* __restrict__ bsums) {
    int b = blockIdx.x, t = threadIdx.x;
    if (b == 0) { if (t == 0) rowptr[0] = 0; return; }
    __shared__ int red[8];
    int v = 0;
    for (int j = t; j < b; j += 256) v += bsums[j];
#pragma unroll
    for (int o = 16; o; o >>= 1) v += __shfl_down_sync(0xffffffffu, v, o);
    if ((t & 31) == 0) red[t >> 5] = v;
    __syncthreads();
    if (t < 8) {
        int y = red[t];
#pragma unroll
        for (int o = 4; o; o >>= 1) y += __shfl_down_sync(0xffu, y, o);
        if (t == 0) red[0] = y;
    }
    __syncthreads();
    int off = red[0];
    int i = b * 256 + t;
    if (i < NN) rowptr[i + 1] += off;
}

__global__ void scatter_kernel(const int* __restrict__ ei,
                               const int* __restrict__ rowptr,
                               int* __restrict__ counts,
                               int* __restrict__ csr_src) {
    int e = blockIdx.x * blockDim.x + threadIdx.x;
    if (e >= ETOT) return;
    int s, d;
    if (e < EDG) { s = ei[e]; d = ei[EDG + e]; }
    else         { s = d = e - EDG; }
    int pos = rowptr[d] + atomicSub(&counts[d], 1) - 1;
    csr_src[pos] = s;
}

// ---------------- cp.async helpers ----------------
__device__ __forceinline__ void cpa16(unsigned int dst, const void* src) {
    asm volatile("cp.async.cg.shared.global [%0], [%1], 16;\n" :: "r"(dst), "l"(src));
}
__device__ __forceinline__ void cp_commit() { asm volatile("cp.async.commit_group;\n"); }
template <int Ngrp>
__device__ __forceinline__ void cp_wait() { asm volatile("cp.async.wait_group %0;\n" :: "n"(Ngrp)); }

__device__ __forceinline__ void mma_f16(float* d, const unsigned* a, const unsigned* b) {
    asm volatile(
        "mma.sync.aligned.m16n8k16.row.col.f32.f16.f16.f32 "
        "{%0,%1,%2,%3}, {%4,%5,%6,%7}, {%8,%9}, {%0,%1,%2,%3};\n"
        : "+f"(d[0]), "+f"(d[1]), "+f"(d[2]), "+f"(d[3])
        : "r"(a[0]), "r"(a[1]), "r"(a[2]), "r"(a[3]), "r"(b[0]), "r"(b[1]));
}

// ---------------- fp16 GEMM (ldmatrix fragments) + fused attention-logit epilogue ----------------
template <int BM, int BN, int WRM, int WRN, int Hv>
__global__ __launch_bounds__(256, 3) void gemm_attn(const __half* __restrict__ A,
                                                    const __half* __restrict__ B,
                                                    __half* __restrict__ C,
                                                    const float* __restrict__ a_s,
                                                    const float* __restrict__ a_d,
                                                    float* __restrict__ al_s,
                                                    float* __restrict__ al_d,
                                                    int M, int N, int K) {
    constexpr int BK = 32;
    constexpr int WM = BM / WRM, WN = BN / WRN;
    constexpr int MT = WM / 16, NT = WN / 8;
    constexpr int AS = BK + 8;                // 40-half stride: ldmatrix row banks {0,20,8,28,16,4,24,12} conflict-free
    constexpr int ACH = BM * 4;
    constexpr int BCH = BN * 4;
    constexpr int ALDA = (ACH + 255) / 256;
    constexpr int BLDB = (BCH + 255) / 256;
    constexpr int HB = BN / 64;

    __shared__ __half As[2][BM * AS];
    __shared__ __half Bs[2][BN * AS];
    __shared__ float sS[BM * HB];
    __shared__ float sD[BM * HB];

    int tid = threadIdx.x, lane = tid & 31, wid = tid >> 5;
    int by = blockIdx.y * BM, bx = blockIdx.x * BN;
    int wm = (wid / WRN) * WM, wn = (wid % WRN) * WN;

    float acc[MT][NT][4];
#pragma unroll
    for (int i = 0; i < MT; i++)
#pragma unroll
        for (int j = 0; j < NT; j++)
#pragma unroll
            for (int r = 0; r < 4; r++) acc[i][j][r] = 0.0f;

    const int ntiles = K / BK;

    auto fetch = [&](int kt, int buf) {
        int k0 = kt * BK;
#pragma unroll
        for (int j = 0; j < ALDA; j++) {
            int i = tid + j * 256;
            if (i < ACH) {
                int row = i >> 2, c = i & 3;
                int gr = by + row; if (gr >= M) gr = M - 1;
                unsigned int dst = (unsigned int)__cvta_generic_to_shared(&As[buf][row * AS + c * 8]);
                cpa16(dst, A + (size_t)gr * K + k0 + c * 8);
            }
        }
#pragma unroll
        for (int j = 0; j < BLDB; j++) {
            int i = tid + j * 256;
            if (i < BCH) {
                int row = i >> 2, c = i & 3;
                unsigned int dst = (unsigned int)__cvta_generic_to_shared(&Bs[buf][row * AS + c * 8]);
                cpa16(dst, B + (size_t)(bx + row) * K + k0 + c * 8);
            }
        }
    };
    auto compute = [&](int buf) {
#pragma unroll
        for (int ks = 0; ks < BK; ks += 16) {
            unsigned af[MT][4], bf[NT][2];
            int cofs = ks + ((lane >> 4) << 3);   // 0 or 8 within the 16-wide k-slice
#pragma unroll
            for (int mt = 0; mt < MT; mt++) {
                int r0 = wm + mt * 16 + (lane & 7) + ((lane >> 3) & 1) * 8;
                unsigned addr = (unsigned)__cvta_generic_to_shared(&As[buf][r0 * AS + cofs]);
                asm volatile("ldmatrix.sync.aligned.m8n8.x4.shared.b16 {%0,%1,%2,%3}, [%4];"
                    : "=r"(af[mt][0]), "=r"(af[mt][1]), "=r"(af[mt][2]), "=r"(af[mt][3])
                    : "r"(addr));
            }
#pragma unroll
            for (int nt = 0; nt < NT; nt += 2) {
                int n0 = wn + nt * 8 + (lane & 15);
                unsigned addr = (unsigned)__cvta_generic_to_shared(&Bs[buf][n0 * AS + cofs]);
                asm volatile("ldmatrix.sync.aligned.m8n8.x4.shared.b16 {%0,%1,%2,%3}, [%4];"
                    : "=r"(bf[nt][0]), "=r"(bf[nt + 1][0]), "=r"(bf[nt][1]), "=r"(bf[nt + 1][1])
                    : "r"(addr));
            }
#pragma unroll
            for (int mt = 0; mt < MT; mt++)
#pragma unroll
                for (int nt = 0; nt < NT; nt++)
                    mma_f16(acc[mt][nt], af[mt], bf[nt]);
        }
    };

    fetch(0, 0);
    cp_commit();
    for (int kt = 0; kt < ntiles; kt++) {
        int buf = kt & 1;
        if (kt + 1 < ntiles) { fetch(kt + 1, buf ^ 1); cp_commit(); cp_wait<1>(); }
        else                 { cp_wait<0>(); }
        __syncthreads();
        compute(buf);
        __syncthreads();
    }

    // ---- store C (fp16) ----
#pragma unroll
    for (int mt = 0; mt < MT; mt++) {
#pragma unroll
        for (int nt = 0; nt < NT; nt++) {
            int r0 = by + wm + mt * 16 + (lane >> 2);
            int c0 = bx + wn + nt * 8 + 2 * (lane & 3);
            if (r0 < M)
                *reinterpret_cast<__half2*>(&C[(size_t)r0 * N + c0]) =
                    __floats2half2_rn(acc[mt][nt][0], acc[mt][nt][1]);
            if (r0 + 8 < M)
                *reinterpret_cast<__half2*>(&C[(size_t)(r0 + 8) * N + c0]) =
                    __floats2half2_rn(acc[mt][nt][2], acc[mt][nt][3]);
        }
    }

    // ---- fused attention-logit epilogue ----
    for (int i = tid; i < BM * HB; i += 256) { sS[i] = 0.f; sD[i] = 0.f; }
    __syncthreads();

    float as0[NT], as1[NT], ad0[NT], ad1[NT];
#pragma unroll
    for (int nt = 0; nt < NT; nt++) {
        int c = bx + wn + nt * 8 + 2 * (lane & 3);
        as0[nt] = a_s[c]; as1[nt] = a_s[c + 1];
        ad0[nt] = a_d[c]; ad1[nt] = a_d[c + 1];
    }
    int hl = wn >> 6;
#pragma unroll
    for (int mt = 0; mt < MT; mt++) {
        float pslo = 0.f, pshi = 0.f, pdlo = 0.f, pdhi = 0.f;
#pragma unroll
        for (int nt = 0; nt < NT; nt++) {
            pslo += acc[mt][nt][0] * as0[nt] + acc[mt][nt][1] * as1[nt];
            pshi += acc[mt][nt][2] * as0[nt] + acc[mt][nt][3] * as1[nt];
            pdlo += acc[mt][nt][0] * ad0[nt] + acc[mt][nt][1] * ad1[nt];
            pdhi += acc[mt][nt][2] * ad0[nt] + acc[mt][nt][3] * ad1[nt];
        }
        pslo += __shfl_xor_sync(0xffffffffu, pslo, 1);
        pslo += __shfl_xor_sync(0xffffffffu, pslo, 2);
        pshi += __shfl_xor_sync(0xffffffffu, pshi, 1);
        pshi += __shfl_xor_sync(0xffffffffu, pshi, 2);
        pdlo += __shfl_xor_sync(0xffffffffu, pdlo, 1);
        pdlo += __shfl_xor_sync(0xffffffffu, pdlo, 2);
        pdhi += __shfl_xor_sync(0xffffffffu, pdhi, 1);
        pdhi += __shfl_xor_sync(0xffffffffu, pdhi, 2);
        if ((lane & 3) == 0) {
            int r = wm + mt * 16 + (lane >> 2);
            atomicAdd(&sS[r * HB + hl], pslo);
            atomicAdd(&sS[(r + 8) * HB + hl], pshi);
            atomicAdd(&sD[r * HB + hl], pdlo);
            atomicAdd(&sD[(r + 8) * HB + hl], pdhi);
        }
    }
    __syncthreads();
    int headbase = bx >> 6;
    for (int i = tid; i < BM * HB; i += 256) {
        int row = i / HB, h2 = i % HB;
        int gr = by + row;
        if (gr < M) {
            al_s[gr * Hv + headbase + h2] = sS[i];
            al_d[gr * Hv + headbase + h2] = sD[i];
        }
    }
}

// ---------------- aggregation (warp per dst), 2-edge unroll ----------------
__device__ __forceinline__ void acc8(float* acc, uint4 u, float wgt) {
    float2 f;
    f = __half22float2(*reinterpret_cast<__half2*>(&u.x)); acc[0] += wgt * f.x; acc[1] += wgt * f.y;
    f = __half22float2(*reinterpret_cast<__half2*>(&u.y)); acc[2] += wgt * f.x; acc[3] += wgt * f.y;
    f = __half22float2(*reinterpret_cast<__half2*>(&u.z)); acc[4] += wgt * f.x; acc[5] += wgt * f.y;
    f = __half22float2(*reinterpret_cast<__half2*>(&u.w)); acc[6] += wgt * f.x; acc[7] += wgt * f.y;
}

template <int HCv, int Hv, int MODE>
__global__ void gat_aggregate_kernel(const __half* __restrict__ hlin,
                                     const int* __restrict__ rowptr,
                                     const int* __restrict__ csr_src,
                                     const float* __restrict__ al_s,
                                     const float* __restrict__ al_d,
                                     const float* __restrict__ bias,
                                     const float* __restrict__ gamma,
                                     const float* __restrict__ beta,
                                     const float* __restrict__ mean,
                                     const float* __restrict__ var,
                                     __half* __restrict__ out,
                                     const int* __restrict__ batch,
                                     float* __restrict__ pooled,
                                     int* __restrict__ cnt) {
    int gw = (blockIdx.x * blockDim.x + threadIdx.x) >> 5;
    int lane = threadIdx.x & 31;
    if (gw >= NN) return;
    const int CPL = HCv / 32;
    int head = (lane * CPL) >> 6;
    float acc[CPL];
#pragma unroll
    for (int j = 0; j < CPL; j++) acc[j] = 0.f;
    float wsum = 0.f;
    float ald_h = __ldg(&al_d[gw * Hv + head]);

    int beg = rowptr[gw], end = rowptr[gw + 1];
    int p = beg;
    for (; p + 2 <= end; p += 2) {
        int s0 = __ldg(&csr_src[p]);
        int s1 = __ldg(&csr_src[p + 1]);
        float e0 = __ldg(&al_s[s0 * Hv + head]) + ald_h;
        float e1 = __ldg(&al_s[s1 * Hv + head]) + ald_h;
        e0 = (e0 > 0.f) ? e0 : SLOPE * e0;
        e1 = (e1 > 0.f) ? e1 : SLOPE * e1;
        float w0 = __expf(e0), w1 = __expf(e1);
        wsum += w0 + w1;
        if (CPL == 8) {
            uint4 u0 = *reinterpret_cast<const uint4*>(hlin + (size_t)s0 * HCv + lane * 8);
            uint4 u1 = *reinterpret_cast<const uint4*>(hlin + (size_t)s1 * HCv + lane * 8);
            acc8(acc, u0, w0);
            acc8(acc, u1, w1);
        } else {
            float2 a = __half22float2(*reinterpret_cast<const __half2*>(hlin + (size_t)s0 * HCv + lane * 2));
            float2 b = __half22float2(*reinterpret_cast<const __half2*>(hlin + (size_t)s1 * HCv + lane * 2));
            acc[0] += w0 * a.x + w1 * b.x;
            acc[1] += w0 * a.y + w1 * b.y;
        }
    }
    if (p < end) {
        int s0 = __ldg(&csr_src[p]);
        float e0 = __ldg(&al_s[s0 * Hv + head]) + ald_h;
        e0 = (e0 > 0.f) ? e0 : SLOPE * e0;
        float w0 = __expf(e0);
        wsum += w0;
        if (CPL == 8) {
            uint4 u0 = *reinterpret_cast<const uint4*>(hlin + (size_t)s0 * HCv + lane * 8);
            acc8(acc, u0, w0);
        } else {
            float2 a = __half22float2(*reinterpret_cast<const __half2*>(hlin + (size_t)s0 * HCv + lane * 2));
            acc[0] += w0 * a.x;
            acc[1] += w0 * a.y;
        }
    }

    float inv = 1.0f / (wsum + 1e-16f);
    if (MODE == 0) {
        float r[CPL];
#pragma unroll
        for (int j = 0; j < CPL; j++) {
            int c = lane * CPL + j;
            float v = acc[j] * inv + bias[c];
            v = (v - mean[c]) * rsqrtf(var[c] + EPS_BN) * gamma[c] + beta[c];
            r[j] = (v > 0.f) ? v : 0.f;
        }
        if (CPL == 8) {
            __half2 p0 = __floats2half2_rn(r[0], r[1]);
            __half2 p1 = __floats2half2_rn(r[2], r[3]);
            __half2 p2 = __floats2half2_rn(r[4], r[5]);
            __half2 p3 = __floats2half2_rn(r[6], r[7]);
            uint4 u;
            u.x = *reinterpret_cast<unsigned*>(&p0);
            u.y = *reinterpret_cast<unsigned*>(&p1);
            u.z = *reinterpret_cast<unsigned*>(&p2);
            u.w = *reinterpret_cast<unsigned*>(&p3);
            *reinterpret_cast<uint4*>(out + (size_t)gw * HCv + lane * 8) = u;
        }
    } else {
        int b = __ldg(&batch[gw]);
        float v0 = acc[0] * inv + bias[lane * 2];
        float v1 = acc[1] * inv + bias[lane * 2 + 1];
        v0 = (v0 > 0.f) ? v0 : 0.f;
        v1 = (v1 > 0.f) ? v1 : 0.f;
        atomicAdd(&pooled[b * HC3 + lane * 2], v0);
        atomicAdd(&pooled[b * HC3 + lane * 2 + 1], v1);
        if (lane == 0) atomicAdd(&cnt[b], 1);
    }
}

// ---------------- final MLP ----------------
__global__ void mlp_kernel(const float* __restrict__ pooled, const int* __restrict__ cnt,
                           const float* __restrict__ w1, const float* __restrict__ b1,
                           const float* __restrict__ w2, const float* __restrict__ b2,
                           float* __restrict__ out) {
    int g = blockIdx.x;
    int t = threadIdx.x;
    __shared__ float m[HC3];
    __shared__ float hid[32];
    float c = (float)cnt[g];
    if (c < 1.0f) c = 1.0f;
    m[t] = pooled[g * HC3 + t] / c;
    __syncthreads();
    if (t < 32) {
        float s = b1[t];
#pragma unroll
        for (int k = 0; k < HC3; k++) s += m[k] * w1[k * 32 + t];
        hid[t] = (s > 0.f) ? s : 0.f;
    }
    __syncthreads();
    if (t < NCLASS) {
        float s = b2[t];
#pragma unroll
        for (int k = 0; k < 32; k++) s += hid[k] * w2[k * NCLASS + t];
        out[g * NCLASS + t] = s;
    }
}

// ---------------- host orchestration ----------------
extern "C" void kernel_launch(void* const* d_in, const int* in_sizes, int n_in,
                              void* d_out, int out_size) {
    const float* x     = (const float*)d_in[0];
    const int*   ei    = (const int*)  d_in[1];
    const int*   batch = (const int*)  d_in[2];
    const float* W1    = (const float*)d_in[3];
    const float* a1s   = (const float*)d_in[4];
    const float* a1d   = (const float*)d_in[5];
    const float* b1    = (const float*)d_in[6];
    const float* bn1g  = (const float*)d_in[7];
    const float* bn1b  = (const float*)d_in[8];
    const float* bn1m  = (const float*)d_in[9];
    const float* bn1v  = (const float*)d_in[10];
    const float* W2    = (const float*)d_in[11];
    const float* a2s   = (const float*)d_in[12];
    const float* a2d   = (const float*)d_in[13];
    const float* b2    = (const float*)d_in[14];
    const float* bn2g  = (const float*)d_in[15];
    const float* bn2b  = (const float*)d_in[16];
    const float* bn2m  = (const float*)d_in[17];
    const float* bn2v  = (const float*)d_in[18];
    const float* W3    = (const float*)d_in[19];
    const float* a3s   = (const float*)d_in[20];
    const float* a3d   = (const float*)d_in[21];
    const float* b3    = (const float*)d_in[22];
    const float* lin1w = (const float*)d_in[23];
    const float* lin1b = (const float*)d_in[24];
    const float* lin2w = (const float*)d_in[25];
    const float* lin2b = (const float*)d_in[26];
    float* out = (float*)d_out;

    __half *xh, *hlin, *hagg, *wt;
    float *als, *ald, *pooled;
    int *counts, *rowptr, *csr_src, *bsums, *cnt;
    cudaGetSymbolAddress((void**)&xh,      g_xh);
    cudaGetSymbolAddress((void**)&hlin,    g_hlin);
    cudaGetSymbolAddress((void**)&hagg,    g_hagg);
    cudaGetSymbolAddress((void**)&wt,      g_wt);
    cudaGetSymbolAddress((void**)&als,     g_als);
    cudaGetSymbolAddress((void**)&ald,     g_ald);
    cudaGetSymbolAddress((void**)&pooled,  g_pooled);
    cudaGetSymbolAddress((void**)&counts,  g_counts);
    cudaGetSymbolAddress((void**)&rowptr,  g_rowptr);
    cudaGetSymbolAddress((void**)&csr_src, g_csr_src);
    cudaGetSymbolAddress((void**)&bsums,   g_bsums);
    cudaGetSymbolAddress((void**)&cnt,     g_cnt);

    const int TB = 256;
    const int edgeBlocks = cdiv(ETOT, TB);
    const int nodeWarpBlocks = cdiv(NN * 32, TB);

    // 0: prep
    prep_kernel<<<cdiv(XHSZ, TB), TB>>>(x, W1, W2, W3, wt, xh, counts, pooled, cnt);
    // 1-2: CSR histogram + scan
    hist_kernel<<<edgeBlocks, TB>>>(ei, counts);
    scan_pass1<<<NBLK1, 256>>>(counts, rowptr, bsums);
    // 3: layer-1 GEMM (profiled launch)
    {
        dim3 grid(HC12 / 128, cdiv(NN, 64));
        gemm_attn<64, 128, 2, 4, 4><<<grid, 256>>>(xh, wt, hlin, a1s, a1d, als, ald, NN, HC12, FIN);
    }
    // 4-5: finish CSR
    scan_fixup<<<NBLK1, 256>>>(rowptr, bsums);
    scatter_kernel<<<edgeBlocks, TB>>>(ei, rowptr, counts, csr_src);
    // 6: layer-1 aggregate
    gat_aggregate_kernel<HC12, 4, 0><<<nodeWarpBlocks, TB>>>(
        hlin, rowptr, csr_src, als, ald, b1, bn1g, bn1b, bn1m, bn1v, hagg, nullptr, nullptr, nullptr);
    // 7-8: layer 2
    {
        dim3 grid(HC12 / 128, cdiv(NN, 64));
        gemm_attn<64, 128, 2, 4, 4><<<grid, 256>>>(hagg, wt + W1SZ, hlin, a2s, a2d, als, ald, NN, HC12, HC12);
        gat_aggregate_kernel<HC12, 4, 0><<<nodeWarpBlocks, TB>>>(
            hlin, rowptr, csr_src, als, ald, b2, bn2g, bn2b, bn2m, bn2v, hagg, nullptr, nullptr, nullptr);
    }
    // 9-10: layer 3 (aggregate fused with mean-pool)
    {
        dim3 grid(HC3 / 64, cdiv(NN, 64));
        gemm_attn<64, 64, 2, 4, 1><<<grid, 256>>>(hagg, wt + W1SZ + W2SZ, hlin, a3s, a3d, als, ald, NN, HC3, HC12);
        gat_aggregate_kernel<HC3, 1, 1><<<nodeWarpBlocks, TB>>>(
            hlin, rowptr, csr_src, als, ald, b3, nullptr, nullptr, nullptr, nullptr,
            nullptr, batch, pooled, cnt);
    }
    // 11: MLP
    mlp_kernel<<<NGRAPH, HC3>>>(pooled, cnt, lin1w, lin1b, lin2w, lin2b, out);

    (void)in_sizes; (void)n_in; (void)out_size;
}